// round 2
// baseline (speedup 1.0000x reference)
#include <cuda_runtime.h>

#define NN      50000
#define FDIM    256
#define H1DIM   128
#define NHEADS  8
#define CDIM2   16

// Scratch (allocation-free rule: __device__ globals)
__device__ float g_hp1[NN * H1DIM];    // layer1 GEMM output (pre-aggregation h)
__device__ float g_acc1[NN * H1DIM];   // layer1 numerator accumulators
__device__ float g_den1[NN * NHEADS];  // layer1 denominators
__device__ float g_as1[NN * NHEADS];
__device__ float g_ad1[NN * NHEADS];
__device__ float g_h1[NN * H1DIM];     // elu(layer1 out)
__device__ float g_h2[NN * CDIM2];     // layer2 GEMM output
__device__ float g_acc2[NN * CDIM2];
__device__ float g_den2[NN];
__device__ float g_as2[NN];
__device__ float g_ad2[NN];

__device__ __forceinline__ void red_add_v4(float* p, float a, float b, float c, float d) {
    asm volatile("red.global.add.v4.f32 [%0], {%1,%2,%3,%4};"
                 :: "l"(p), "f"(a), "f"(b), "f"(c), "f"(d) : "memory");
}
__device__ __forceinline__ void red_add_f32(float* p, float v) {
    asm volatile("red.global.add.f32 [%0], %1;" :: "l"(p), "f"(v) : "memory");
}

// ---------------------------------------------------------------------------
// GEMM1: g_hp1[N,128] = x[N,256] @ W1[256,128]   (no bias here; bias is post-agg)
// 128x128x32 tiles, 256 threads, 8x8 microtiles.
// ---------------------------------------------------------------------------
__global__ void gemm1_kernel(const float* __restrict__ X, const float* __restrict__ W) {
    __shared__ __align__(16) float As[32][132];  // [k][m], padded
    __shared__ __align__(16) float Bs[32][128];  // [k][n]
    const int tid = threadIdx.x;
    const int row0 = blockIdx.x * 128;
    const int tx = tid & 15, ty = tid >> 4;

    float acc[8][8];
#pragma unroll
    for (int i = 0; i < 8; i++)
#pragma unroll
        for (int j = 0; j < 8; j++) acc[i][j] = 0.f;

    for (int k0 = 0; k0 < FDIM; k0 += 32) {
#pragma unroll
        for (int t = 0; t < 4; t++) {
            int i = tid + t * 256;           // 1024 float4s for A tile
            int r = i >> 3, c4 = (i & 7) << 2;
            float4 v = make_float4(0.f, 0.f, 0.f, 0.f);
            int gr = row0 + r;
            if (gr < NN) v = *(const float4*)(X + (size_t)gr * FDIM + k0 + c4);
            As[c4 + 0][r] = v.x; As[c4 + 1][r] = v.y;
            As[c4 + 2][r] = v.z; As[c4 + 3][r] = v.w;
        }
#pragma unroll
        for (int t = 0; t < 4; t++) {
            int i = tid + t * 256;           // 1024 float4s for B tile
            int r = i >> 5, c = (i & 31) << 2;
            *(float4*)&Bs[r][c] = *(const float4*)(W + (size_t)(k0 + r) * H1DIM + c);
        }
        __syncthreads();
#pragma unroll
        for (int k = 0; k < 32; k++) {
            float a[8], b[8];
#pragma unroll
            for (int i = 0; i < 8; i++) a[i] = As[k][ty * 8 + i];
#pragma unroll
            for (int j = 0; j < 8; j++) b[j] = Bs[k][tx * 8 + j];
#pragma unroll
            for (int i = 0; i < 8; i++)
#pragma unroll
                for (int j = 0; j < 8; j++) acc[i][j] += a[i] * b[j];
        }
        __syncthreads();
    }
#pragma unroll
    for (int i = 0; i < 8; i++) {
        int gr = row0 + ty * 8 + i;
        if (gr < NN) {
            float* o = g_hp1 + (size_t)gr * H1DIM + tx * 8;
            *(float4*)(o + 0) = make_float4(acc[i][0], acc[i][1], acc[i][2], acc[i][3]);
            *(float4*)(o + 4) = make_float4(acc[i][4], acc[i][5], acc[i][6], acc[i][7]);
        }
    }
}

// ---------------------------------------------------------------------------
// alpha1: per-node attention logits; also zeroes acc1/den1. One warp per node.
// ---------------------------------------------------------------------------
__global__ void alpha1_kernel(const float* __restrict__ att_src, const float* __restrict__ att_dst) {
    int gw = (blockIdx.x * blockDim.x + threadIdx.x) >> 5;
    int lane = threadIdx.x & 31;
    if (gw >= NN) return;
    int head = lane >> 2, sub = lane & 3;
    float4 h = *(const float4*)(g_hp1 + (size_t)gw * H1DIM + lane * 4);
    const float* As = att_src + head * 16 + sub * 4;
    const float* Ad = att_dst + head * 16 + sub * 4;
    float s = h.x * As[0] + h.y * As[1] + h.z * As[2] + h.w * As[3];
    float d = h.x * Ad[0] + h.y * Ad[1] + h.z * Ad[2] + h.w * Ad[3];
    s += __shfl_xor_sync(0xffffffffu, s, 1);
    s += __shfl_xor_sync(0xffffffffu, s, 2);
    d += __shfl_xor_sync(0xffffffffu, d, 1);
    d += __shfl_xor_sync(0xffffffffu, d, 2);
    if (sub == 0) { g_as1[gw * 8 + head] = s; g_ad1[gw * 8 + head] = d; }
    *(float4*)(g_acc1 + (size_t)gw * H1DIM + lane * 4) = make_float4(0.f, 0.f, 0.f, 0.f);
    if (lane < 8) g_den1[gw * 8 + lane] = 0.f;
}

// ---------------------------------------------------------------------------
// edge1: one warp per edge (incl. self-loops). 128 features via v4 red.
// ---------------------------------------------------------------------------
__global__ void edge1_kernel(const int* __restrict__ ei, int E) {
    const int total = E + NN;
    const int lane = threadIdx.x & 31;
    const int gw = (blockIdx.x * blockDim.x + threadIdx.x) >> 5;
    const int nw = (gridDim.x * blockDim.x) >> 5;
    for (int e = gw; e < total; e += nw) {
        int s, d;
        if (e < E) { s = ei[e]; d = ei[E + e]; } else { s = e - E; d = s; }
        float wh = 0.f;
        if (lane < 8) {
            float t = g_as1[s * 8 + lane] + g_ad1[d * 8 + lane];
            t = t > 0.f ? t : 0.2f * t;                 // leaky relu
            wh = __expf(t);
            red_add_f32(g_den1 + d * 8 + lane, wh);
        }
        float w = __shfl_sync(0xffffffffu, wh, lane >> 2);
        float4 h = *(const float4*)(g_hp1 + (size_t)s * H1DIM + lane * 4);
        red_add_v4(g_acc1 + (size_t)d * H1DIM + lane * 4, w * h.x, w * h.y, w * h.z, w * h.w);
    }
}

// ---------------------------------------------------------------------------
// node1: h1 = elu(acc1/den1 + b1)
// ---------------------------------------------------------------------------
__global__ void node1_kernel(const float* __restrict__ b1) {
    int idx = blockIdx.x * blockDim.x + threadIdx.x;
    if (idx >= NN * 32) return;
    int n = idx >> 5, g = idx & 31;
    float4 a = *(const float4*)(g_acc1 + (size_t)n * H1DIM + g * 4);
    float inv = __frcp_rn(g_den1[n * 8 + (g >> 2)]);
    const float* bb = b1 + g * 4;
    float v0 = a.x * inv + bb[0];
    float v1 = a.y * inv + bb[1];
    float v2 = a.z * inv + bb[2];
    float v3 = a.w * inv + bb[3];
    v0 = v0 > 0.f ? v0 : expm1f(v0);
    v1 = v1 > 0.f ? v1 : expm1f(v1);
    v2 = v2 > 0.f ? v2 : expm1f(v2);
    v3 = v3 > 0.f ? v3 : expm1f(v3);
    *(float4*)(g_h1 + (size_t)n * H1DIM + g * 4) = make_float4(v0, v1, v2, v3);
}

// ---------------------------------------------------------------------------
// GEMM2 + alpha2 fused: h2 = h1 @ W2; per-node logits; zero acc2/den2.
// 16 rows x 16 cols per block (256 threads, one output each).
// ---------------------------------------------------------------------------
__global__ void gemm2_kernel(const float* __restrict__ W2,
                             const float* __restrict__ as2w, const float* __restrict__ ad2w) {
    __shared__ __align__(16) float Ws[128 * 16];
    __shared__ __align__(16) float Hs[16][132];
    const int tid = threadIdx.x;
    const int row0 = blockIdx.x * 16;
#pragma unroll
    for (int t = 0; t < 2; t++) {
        int i = (tid + t * 256) * 4;
        *(float4*)&Ws[i] = *(const float4*)(W2 + i);
    }
#pragma unroll
    for (int t = 0; t < 2; t++) {
        int i = tid + t * 256;               // 512 float4s = 16 rows x 32
        int r = i >> 5, c = (i & 31) << 2;
        float4 v = make_float4(0.f, 0.f, 0.f, 0.f);
        int gr = row0 + r;
        if (gr < NN) v = *(const float4*)(g_h1 + (size_t)gr * H1DIM + c);
        *(float4*)&Hs[r][c] = v;
    }
    __syncthreads();
    const int r = tid >> 4, c = tid & 15;
    float s = 0.f;
#pragma unroll
    for (int k = 0; k < 128; k++) s += Hs[r][k] * Ws[k * 16 + c];
    float sv = s * as2w[c], dv = s * ad2w[c];
#pragma unroll
    for (int off = 8; off >= 1; off >>= 1) {
        sv += __shfl_down_sync(0xffffffffu, sv, off, 16);
        dv += __shfl_down_sync(0xffffffffu, dv, off, 16);
    }
    int gr = row0 + r;
    if (gr < NN) {
        g_h2[gr * 16 + c] = s;
        g_acc2[gr * 16 + c] = 0.f;
        if (c == 0) { g_as2[gr] = sv; g_ad2[gr] = dv; g_den2[gr] = 0.f; }
    }
}

// ---------------------------------------------------------------------------
// edge2: 4 lanes per edge (16 feats = one v4 per lane), 8 edges per warp.
// ---------------------------------------------------------------------------
__global__ void edge2_kernel(const int* __restrict__ ei, int E) {
    const int total = E + NN;
    const int lane = threadIdx.x & 31;
    const int gw = (blockIdx.x * blockDim.x + threadIdx.x) >> 5;
    const int nw = (gridDim.x * blockDim.x) >> 5;
    const int sub = lane >> 2, lo = lane & 3;
    for (int eb = gw * 8; eb < total; eb += nw * 8) {
        int e = eb + sub;
        if (e < total) {
            int s, d;
            if (e < E) { s = ei[e]; d = ei[E + e]; } else { s = e - E; d = s; }
            float t = g_as2[s] + g_ad2[d];
            t = t > 0.f ? t : 0.2f * t;
            float w = __expf(t);
            if (lo == 0) red_add_f32(g_den2 + d, w);
            float4 h = *(const float4*)(g_h2 + (size_t)s * 16 + lo * 4);
            red_add_v4(g_acc2 + (size_t)d * 16 + lo * 4, w * h.x, w * h.y, w * h.z, w * h.w);
        }
    }
}

// ---------------------------------------------------------------------------
// node2: out = acc2/den2 + b2   (heads=1, mean == identity)
// ---------------------------------------------------------------------------
__global__ void node2_kernel(const float* __restrict__ b2, float* __restrict__ out) {
    int idx = blockIdx.x * blockDim.x + threadIdx.x;
    if (idx >= NN * 16) return;
    int n = idx >> 4, c = idx & 15;
    out[idx] = g_acc2[idx] * __frcp_rn(g_den2[n]) + b2[c];
}

// ---------------------------------------------------------------------------
extern "C" void kernel_launch(void* const* d_in, const int* in_sizes, int n_in,
                              void* d_out, int out_size) {
    const float* x   = (const float*)d_in[0];
    const int*   ei  = (const int*)d_in[1];
    const float* W1  = (const float*)d_in[2];
    const float* as1 = (const float*)d_in[3];
    const float* ad1 = (const float*)d_in[4];
    const float* b1  = (const float*)d_in[5];
    const float* W2  = (const float*)d_in[6];
    const float* as2 = (const float*)d_in[7];
    const float* ad2 = (const float*)d_in[8];
    const float* b2  = (const float*)d_in[9];
    const int E = in_sizes[1] / 2;

    gemm1_kernel<<<(NN + 127) / 128, 256>>>(x, W1);
    alpha1_kernel<<<(NN * 32 + 255) / 256, 256>>>(as1, ad1);
    edge1_kernel<<<2048, 256>>>(ei, E);
    node1_kernel<<<(NN * 32 + 255) / 256, 256>>>(b1);
    gemm2_kernel<<<(NN + 15) / 16, 256>>>(W2, as2, ad2);
    edge2_kernel<<<1024, 256>>>(ei, E);
    node2_kernel<<<(NN * 16 + 255) / 256, 256>>>(b2, (float*)d_out);
}

// round 3
// speedup vs baseline: 1.1954x; 1.1954x over previous
#include <cuda_runtime.h>

#define NN      50000
#define FDIM    256
#define H1DIM   128
#define NHEADS  8
#define CDIM2   16
#define EMAX    1100000

// ---- scratch (__device__ globals; no allocation allowed) -------------------
__device__ float g_hp1[NN * H1DIM];    // layer1 GEMM output (pre-aggregation)
__device__ float g_as1[NN * NHEADS];
__device__ float g_ad1[NN * NHEADS];
__device__ float g_h1[NN * H1DIM];     // elu(aggregated layer1)
__device__ float g_h2[NN * CDIM2];     // layer2 GEMM output
__device__ float g_as2[NN];
__device__ float g_ad2[NN];
// CSR (built every launch; graph incl. self-loops, grouped by dst)
__device__ int g_deg[NN];
__device__ int g_off[NN + 1];
__device__ int g_cur[NN];
__device__ int g_eidx[EMAX];           // src node per incoming edge

__device__ __forceinline__ unsigned f2tf32(float x) {
    unsigned r; asm("cvt.rna.tf32.f32 %0, %1;" : "=r"(r) : "f"(x)); return r;
}

// ---------------------------------------------------------------------------
// CSR build: zero -> histogram -> scan -> scatter
// ---------------------------------------------------------------------------
__global__ void zero_deg_kernel() {
    int i = blockIdx.x * blockDim.x + threadIdx.x;
    if (i < NN) g_deg[i] = 0;
}

__global__ void hist_kernel(const int* __restrict__ ei, int E) {
    int i = blockIdx.x * blockDim.x + threadIdx.x;
    int total = E + NN;
    if (i >= total) return;
    int d = (i < E) ? ei[E + i] : (i - E);
    atomicAdd(&g_deg[d], 1);
}

__global__ void scan_kernel() {
    __shared__ int buf[1024];
    __shared__ int carry;
    if (threadIdx.x == 0) carry = 0;
    __syncthreads();
    for (int base = 0; base < NN; base += 1024) {
        int i = base + threadIdx.x;
        int v = (i < NN) ? g_deg[i] : 0;
        buf[threadIdx.x] = v;
        __syncthreads();
#pragma unroll
        for (int off = 1; off < 1024; off <<= 1) {
            int t = (threadIdx.x >= off) ? buf[threadIdx.x - off] : 0;
            __syncthreads();
            buf[threadIdx.x] += t;
            __syncthreads();
        }
        int excl = carry + buf[threadIdx.x] - v;
        if (i < NN) { g_off[i] = excl; g_cur[i] = excl; }
        __syncthreads();
        if (threadIdx.x == 1023) carry += buf[1023];
        __syncthreads();
    }
    if (threadIdx.x == 0) g_off[NN] = carry;
}

__global__ void scatter_kernel(const int* __restrict__ ei, int E) {
    int i = blockIdx.x * blockDim.x + threadIdx.x;
    int total = E + NN;
    if (i >= total) return;
    int s, d;
    if (i < E) { s = ei[i]; d = ei[E + i]; } else { s = i - E; d = s; }
    int pos = atomicAdd(&g_cur[d], 1);
    g_eidx[pos] = s;
}

// ---------------------------------------------------------------------------
// GEMM1 (tf32 MMA): g_hp1[N,128] = x[N,256] @ W1[256,128]
// 128x128 tile, 8 warps in 4(m)x2(n); each warp 32x64 via m16n8k8.
// ---------------------------------------------------------------------------
__global__ void __launch_bounds__(256) gemm1_kernel(const float* __restrict__ X,
                                                    const float* __restrict__ W) {
    __shared__ __align__(16) float As[128][36];   // tf32 bits, row-major [m][k]
    __shared__ __align__(16) float Bt[128][36];   // tf32 bits, [n][k]
    const int tid = threadIdx.x;
    const int warp = tid >> 5, lane = tid & 31;
    const int wm = warp >> 1, wn = warp & 1;
    const int row0 = blockIdx.x * 128;
    const int gid = lane >> 2, qid = lane & 3;

    float acc[2][8][4];
#pragma unroll
    for (int mt = 0; mt < 2; mt++)
#pragma unroll
        for (int nt = 0; nt < 8; nt++)
#pragma unroll
            for (int j = 0; j < 4; j++) acc[mt][nt][j] = 0.f;

    for (int k0 = 0; k0 < FDIM; k0 += 32) {
        // A tile: 128x32, 1024 float4 loads
#pragma unroll
        for (int t = 0; t < 4; t++) {
            int i = tid + t * 256;
            int r = i >> 3, c = (i & 7) << 2;
            float4 v = make_float4(0.f, 0.f, 0.f, 0.f);
            if (row0 + r < NN) v = *(const float4*)(X + (size_t)(row0 + r) * FDIM + k0 + c);
            float4 o;
            o.x = __uint_as_float(f2tf32(v.x));
            o.y = __uint_as_float(f2tf32(v.y));
            o.z = __uint_as_float(f2tf32(v.z));
            o.w = __uint_as_float(f2tf32(v.w));
            *(float4*)&As[r][c] = o;
        }
        // B tile: 32(k)x128(n), stored transposed [n][k]
#pragma unroll
        for (int t = 0; t < 4; t++) {
            int i = tid + t * 256;
            int r = i & 31;             // k within tile
            int c = (i >> 5) << 2;      // n
            float4 v = *(const float4*)(W + (size_t)(k0 + r) * H1DIM + c);
            Bt[c + 0][r] = __uint_as_float(f2tf32(v.x));
            Bt[c + 1][r] = __uint_as_float(f2tf32(v.y));
            Bt[c + 2][r] = __uint_as_float(f2tf32(v.z));
            Bt[c + 3][r] = __uint_as_float(f2tf32(v.w));
        }
        __syncthreads();
#pragma unroll
        for (int kk = 0; kk < 4; kk++) {
            const int k = kk * 8;
            unsigned a[2][4], b[8][2];
#pragma unroll
            for (int mt = 0; mt < 2; mt++) {
                int rw = wm * 32 + mt * 16 + gid;
                a[mt][0] = __float_as_uint(As[rw][k + qid]);
                a[mt][1] = __float_as_uint(As[rw + 8][k + qid]);
                a[mt][2] = __float_as_uint(As[rw][k + 4 + qid]);
                a[mt][3] = __float_as_uint(As[rw + 8][k + 4 + qid]);
            }
#pragma unroll
            for (int nt = 0; nt < 8; nt++) {
                int cl = wn * 64 + nt * 8 + gid;
                b[nt][0] = __float_as_uint(Bt[cl][k + qid]);
                b[nt][1] = __float_as_uint(Bt[cl][k + 4 + qid]);
            }
#pragma unroll
            for (int mt = 0; mt < 2; mt++)
#pragma unroll
                for (int nt = 0; nt < 8; nt++) {
                    asm volatile(
                        "mma.sync.aligned.m16n8k8.row.col.f32.tf32.tf32.f32 "
                        "{%0,%1,%2,%3}, {%4,%5,%6,%7}, {%8,%9}, {%0,%1,%2,%3};\n"
                        : "+f"(acc[mt][nt][0]), "+f"(acc[mt][nt][1]),
                          "+f"(acc[mt][nt][2]), "+f"(acc[mt][nt][3])
                        : "r"(a[mt][0]), "r"(a[mt][1]), "r"(a[mt][2]), "r"(a[mt][3]),
                          "r"(b[nt][0]), "r"(b[nt][1]));
                }
        }
        __syncthreads();
    }
    // epilogue: c0/c1 at (row, 2q), c2/c3 at (row+8, 2q)
#pragma unroll
    for (int mt = 0; mt < 2; mt++) {
        int rw = row0 + wm * 32 + mt * 16 + gid;
#pragma unroll
        for (int nt = 0; nt < 8; nt++) {
            int cl = wn * 64 + nt * 8 + qid * 2;
            if (rw < NN)
                *(float2*)(g_hp1 + (size_t)rw * H1DIM + cl) =
                    make_float2(acc[mt][nt][0], acc[mt][nt][1]);
            if (rw + 8 < NN)
                *(float2*)(g_hp1 + (size_t)(rw + 8) * H1DIM + cl) =
                    make_float2(acc[mt][nt][2], acc[mt][nt][3]);
        }
    }
}

// ---------------------------------------------------------------------------
// alpha1: per-node attention logits. One warp per node.
// ---------------------------------------------------------------------------
__global__ void alpha1_kernel(const float* __restrict__ att_src, const float* __restrict__ att_dst) {
    int gw = (blockIdx.x * blockDim.x + threadIdx.x) >> 5;
    int lane = threadIdx.x & 31;
    if (gw >= NN) return;
    int head = lane >> 2, sub = lane & 3;
    float4 h = *(const float4*)(g_hp1 + (size_t)gw * H1DIM + lane * 4);
    const float* As = att_src + head * 16 + sub * 4;
    const float* Ad = att_dst + head * 16 + sub * 4;
    float s = h.x * As[0] + h.y * As[1] + h.z * As[2] + h.w * As[3];
    float d = h.x * Ad[0] + h.y * Ad[1] + h.z * Ad[2] + h.w * Ad[3];
    s += __shfl_xor_sync(0xffffffffu, s, 1);
    s += __shfl_xor_sync(0xffffffffu, s, 2);
    d += __shfl_xor_sync(0xffffffffu, d, 1);
    d += __shfl_xor_sync(0xffffffffu, d, 2);
    if (sub == 0) { g_as1[gw * 8 + head] = s; g_ad1[gw * 8 + head] = d; }
}

// ---------------------------------------------------------------------------
// agg1: CSR gather-aggregate + normalize + bias + ELU (fuses old edge1+node1).
// One warp per dst node; lane owns 4 features; lanes 0-7 own head weights.
// ---------------------------------------------------------------------------
__global__ void __launch_bounds__(256) agg1_kernel(const float* __restrict__ b1) {
    int gw = (blockIdx.x * blockDim.x + threadIdx.x) >> 5;
    int lane = threadIdx.x & 31;
    if (gw >= NN) return;
    int beg = g_off[gw], end = g_off[gw + 1];
    float myad = (lane < 8) ? g_ad1[gw * 8 + lane] : 0.f;
    float a0 = 0.f, a1 = 0.f, a2 = 0.f, a3 = 0.f, den = 0.f;
    int s = (beg < end) ? g_eidx[beg] : 0;
    for (int p = beg; p < end; p++) {
        int s_next = (p + 1 < end) ? g_eidx[p + 1] : 0;
        float wh = 0.f;
        if (lane < 8) {
            float t = g_as1[s * 8 + lane] + myad;
            t = t > 0.f ? t : 0.2f * t;
            wh = __expf(t);
            den += wh;
        }
        float w = __shfl_sync(0xffffffffu, wh, lane >> 2);
        float4 h = *(const float4*)(g_hp1 + (size_t)s * H1DIM + lane * 4);
        a0 += w * h.x; a1 += w * h.y; a2 += w * h.z; a3 += w * h.w;
        s = s_next;
    }
    float dh = __shfl_sync(0xffffffffu, den, lane >> 2);
    float inv = __frcp_rn(dh);
    const float* bb = b1 + lane * 4;
    float v0 = a0 * inv + bb[0];
    float v1 = a1 * inv + bb[1];
    float v2 = a2 * inv + bb[2];
    float v3 = a3 * inv + bb[3];
    v0 = v0 > 0.f ? v0 : expm1f(v0);
    v1 = v1 > 0.f ? v1 : expm1f(v1);
    v2 = v2 > 0.f ? v2 : expm1f(v2);
    v3 = v3 > 0.f ? v3 : expm1f(v3);
    *(float4*)(g_h1 + (size_t)gw * H1DIM + lane * 4) = make_float4(v0, v1, v2, v3);
}

// ---------------------------------------------------------------------------
// GEMM2 + alpha2 fused: h2 = h1 @ W2 ; per-node logits.
// ---------------------------------------------------------------------------
__global__ void __launch_bounds__(256) gemm2_kernel(const float* __restrict__ W2,
                             const float* __restrict__ as2w, const float* __restrict__ ad2w) {
    __shared__ __align__(16) float Ws[128 * 16];
    __shared__ __align__(16) float Hs[16][132];
    const int tid = threadIdx.x;
    const int row0 = blockIdx.x * 16;
#pragma unroll
    for (int t = 0; t < 2; t++) {
        int i = (tid + t * 256) * 4;
        *(float4*)&Ws[i] = *(const float4*)(W2 + i);
    }
#pragma unroll
    for (int t = 0; t < 2; t++) {
        int i = tid + t * 256;
        int r = i >> 5, c = (i & 31) << 2;
        float4 v = make_float4(0.f, 0.f, 0.f, 0.f);
        int gr = row0 + r;
        if (gr < NN) v = *(const float4*)(g_h1 + (size_t)gr * H1DIM + c);
        *(float4*)&Hs[r][c] = v;
    }
    __syncthreads();
    const int r = tid >> 4, c = tid & 15;
    float s = 0.f;
#pragma unroll
    for (int k = 0; k < 128; k++) s += Hs[r][k] * Ws[k * 16 + c];
    float sv = s * as2w[c], dv = s * ad2w[c];
#pragma unroll
    for (int off = 8; off >= 1; off >>= 1) {
        sv += __shfl_down_sync(0xffffffffu, sv, off, 16);
        dv += __shfl_down_sync(0xffffffffu, dv, off, 16);
    }
    int gr = row0 + r;
    if (gr < NN) {
        g_h2[gr * 16 + c] = s;
        if (c == 0) { g_as2[gr] = sv; g_ad2[gr] = dv; }
    }
}

// ---------------------------------------------------------------------------
// agg2: CSR gather-aggregate for layer2 + bias -> final output.
// One warp per dst node; two 16-lane groups each handle one edge per iter.
// ---------------------------------------------------------------------------
__global__ void __launch_bounds__(256) agg2_kernel(const float* __restrict__ b2,
                                                   float* __restrict__ out) {
    int gw = (blockIdx.x * blockDim.x + threadIdx.x) >> 5;
    int lane = threadIdx.x & 31;
    if (gw >= NN) return;
    int beg = g_off[gw], end = g_off[gw + 1];
    int grp = lane >> 4, fl = lane & 15;
    float ad = g_ad2[gw];
    float acc = 0.f, den = 0.f;
    for (int p = beg + grp; p < end; p += 2) {
        int s = g_eidx[p];
        float t = g_as2[s] + ad;
        t = t > 0.f ? t : 0.2f * t;
        float w = __expf(t);
        den += w;
        acc += w * g_h2[s * 16 + fl];
    }
    acc += __shfl_xor_sync(0xffffffffu, acc, 16);
    den += __shfl_xor_sync(0xffffffffu, den, 16);
    if (grp == 0) out[gw * 16 + fl] = acc * __frcp_rn(den) + b2[fl];
}

// ---------------------------------------------------------------------------
extern "C" void kernel_launch(void* const* d_in, const int* in_sizes, int n_in,
                              void* d_out, int out_size) {
    const float* x   = (const float*)d_in[0];
    const int*   ei  = (const int*)d_in[1];
    const float* W1  = (const float*)d_in[2];
    const float* as1 = (const float*)d_in[3];
    const float* ad1 = (const float*)d_in[4];
    const float* b1  = (const float*)d_in[5];
    const float* W2  = (const float*)d_in[6];
    const float* as2 = (const float*)d_in[7];
    const float* ad2 = (const float*)d_in[8];
    const float* b2  = (const float*)d_in[9];
    const int E = in_sizes[1] / 2;
    const int total = E + NN;

    zero_deg_kernel<<<(NN + 255) / 256, 256>>>();
    hist_kernel<<<(total + 255) / 256, 256>>>(ei, E);
    scan_kernel<<<1, 1024>>>();
    scatter_kernel<<<(total + 255) / 256, 256>>>(ei, E);

    gemm1_kernel<<<(NN + 127) / 128, 256>>>(x, W1);
    alpha1_kernel<<<(NN * 32 + 255) / 256, 256>>>(as1, ad1);
    agg1_kernel<<<(NN * 32 + 255) / 256, 256>>>(b1);
    gemm2_kernel<<<(NN + 15) / 16, 256>>>(W2, as2, ad2);
    agg2_kernel<<<(NN * 32 + 255) / 256, 256>>>(b2, (float*)d_out);
}

// round 4
// speedup vs baseline: 1.7685x; 1.4795x over previous
#include <cuda_runtime.h>

#define NN      50000
#define FDIM    256
#define H1DIM   128
#define NHEADS  8
#define CDIM2   16
#define EMAX    1100000
#define NBLK    196              // ceil(50000/256)

// ---- scratch (__device__ globals; no allocation allowed) -------------------
__device__ float g_hp1[NN * H1DIM];
__device__ float g_as1[NN * NHEADS];
__device__ float g_ad1[NN * NHEADS];
__device__ float g_h1[NN * H1DIM];
__device__ float g_h2[NN * CDIM2];
__device__ float g_as2[NN];
__device__ float g_ad2[NN];
__device__ int g_deg[NN];
__device__ int g_off[NN + 1];
__device__ int g_cur[NN];
__device__ int g_bsum[NBLK];
__device__ int g_boff[NBLK];
__device__ int g_eidx[EMAX];

__device__ __forceinline__ unsigned f2tf32(float x) {
    unsigned r; asm("cvt.rna.tf32.f32 %0, %1;" : "=r"(r) : "f"(x)); return r;
}

// ---------------------------------------------------------------------------
// CSR build
// ---------------------------------------------------------------------------
__global__ void zero_deg_kernel() {
    int i = blockIdx.x * blockDim.x + threadIdx.x;
    if (i < NN) g_deg[i] = 0;
}

// 4 edges per thread (coalesced; batched independent atomics for ILP)
__global__ void hist_kernel(const int* __restrict__ ei, int E) {
    int i0 = (blockIdx.x * blockDim.x + threadIdx.x) * 4;
    if (i0 >= E) return;
    int n = min(4, E - i0);
    int d0, d1, d2, d3;
    d0 = ei[E + i0];
    if (n > 1) d1 = ei[E + i0 + 1];
    if (n > 2) d2 = ei[E + i0 + 2];
    if (n > 3) d3 = ei[E + i0 + 3];
    atomicAdd(&g_deg[d0], 1);
    if (n > 1) atomicAdd(&g_deg[d1], 1);
    if (n > 2) atomicAdd(&g_deg[d2], 1);
    if (n > 3) atomicAdd(&g_deg[d3], 1);
}

// per-block reduction of (deg+1)
__global__ void scanA_kernel() {
    __shared__ int buf[256];
    int i = blockIdx.x * 256 + threadIdx.x;
    int v = (i < NN) ? g_deg[i] + 1 : 0;   // +1 = self-loop
    buf[threadIdx.x] = v;
    __syncthreads();
#pragma unroll
    for (int off = 128; off >= 1; off >>= 1) {
        if (threadIdx.x < off) buf[threadIdx.x] += buf[threadIdx.x + off];
        __syncthreads();
    }
    if (threadIdx.x == 0) g_bsum[blockIdx.x] = buf[0];
}

// scan of NBLK block sums
__global__ void scanB_kernel() {
    __shared__ int buf[256];
    int t = threadIdx.x;
    int v = (t < NBLK) ? g_bsum[t] : 0;
    buf[t] = v;
    __syncthreads();
#pragma unroll
    for (int off = 1; off < 256; off <<= 1) {
        int n = (t >= off) ? buf[t - off] : 0;
        __syncthreads();
        buf[t] += n;
        __syncthreads();
    }
    if (t < NBLK) g_boff[t] = buf[t] - v;      // exclusive
    if (t == NBLK - 1) g_off[NN] = buf[t];     // total
}

// per-block scan + global offset -> g_off / g_cur
__global__ void scanC_kernel() {
    __shared__ int wsum[8];
    int t = threadIdx.x, lane = t & 31, wid = t >> 5;
    int i = blockIdx.x * 256 + t;
    int v = (i < NN) ? g_deg[i] + 1 : 0;
    int incl = v;
#pragma unroll
    for (int off = 1; off < 32; off <<= 1) {
        int n = __shfl_up_sync(0xffffffffu, incl, off);
        if (lane >= off) incl += n;
    }
    if (lane == 31) wsum[wid] = incl;
    __syncthreads();
    if (wid == 0 && lane < 8) {
        int s = wsum[lane];
#pragma unroll
        for (int off = 1; off < 8; off <<= 1) {
            int n = __shfl_up_sync(0x000000ffu, s, off);
            if (lane >= off) s += n;
        }
        wsum[lane] = s;
    }
    __syncthreads();
    int woff = (wid > 0) ? wsum[wid - 1] : 0;
    int excl = g_boff[blockIdx.x] + woff + incl - v;
    if (i < NN) { g_off[i] = excl; g_cur[i] = excl; }
}

// 2 real edges per thread + self-loop range (+ odd-E tail)
__global__ void scatter_kernel(const int* __restrict__ ei, int E) {
    int pairs = E >> 1;
    int idx = blockIdx.x * blockDim.x + threadIdx.x;
    if (idx < pairs) {
        int e = idx * 2;
        int s0 = ei[e], s1 = ei[e + 1];
        int d0 = ei[E + e], d1 = ei[E + e + 1];
        int p0 = atomicAdd(&g_cur[d0], 1);
        int p1 = atomicAdd(&g_cur[d1], 1);
        g_eidx[p0] = s0;
        g_eidx[p1] = s1;
    } else if (idx < pairs + NN) {
        int n = idx - pairs;
        int p = atomicAdd(&g_cur[n], 1);
        g_eidx[p] = n;
    } else if ((E & 1) && idx == pairs + NN) {
        int s = ei[E - 1], d = ei[E + E - 1];
        int p = atomicAdd(&g_cur[d], 1);
        g_eidx[p] = s;
    }
}

// ---------------------------------------------------------------------------
// GEMM1 (tf32 MMA): g_hp1[N,128] = x[N,256] @ W1[256,128]
// ---------------------------------------------------------------------------
__global__ void __launch_bounds__(256) gemm1_kernel(const float* __restrict__ X,
                                                    const float* __restrict__ W) {
    __shared__ __align__(16) float As[128][36];
    __shared__ __align__(16) float Bt[128][36];
    const int tid = threadIdx.x;
    const int warp = tid >> 5, lane = tid & 31;
    const int wm = warp >> 1, wn = warp & 1;
    const int row0 = blockIdx.x * 128;
    const int gid = lane >> 2, qid = lane & 3;

    float acc[2][8][4];
#pragma unroll
    for (int mt = 0; mt < 2; mt++)
#pragma unroll
        for (int nt = 0; nt < 8; nt++)
#pragma unroll
            for (int j = 0; j < 4; j++) acc[mt][nt][j] = 0.f;

    for (int k0 = 0; k0 < FDIM; k0 += 32) {
#pragma unroll
        for (int t = 0; t < 4; t++) {
            int i = tid + t * 256;
            int r = i >> 3, c = (i & 7) << 2;
            float4 v = make_float4(0.f, 0.f, 0.f, 0.f);
            if (row0 + r < NN) v = *(const float4*)(X + (size_t)(row0 + r) * FDIM + k0 + c);
            float4 o;
            o.x = __uint_as_float(f2tf32(v.x));
            o.y = __uint_as_float(f2tf32(v.y));
            o.z = __uint_as_float(f2tf32(v.z));
            o.w = __uint_as_float(f2tf32(v.w));
            *(float4*)&As[r][c] = o;
        }
#pragma unroll
        for (int t = 0; t < 4; t++) {
            int i = tid + t * 256;
            int r = i & 31;
            int c = (i >> 5) << 2;
            float4 v = *(const float4*)(W + (size_t)(k0 + r) * H1DIM + c);
            Bt[c + 0][r] = __uint_as_float(f2tf32(v.x));
            Bt[c + 1][r] = __uint_as_float(f2tf32(v.y));
            Bt[c + 2][r] = __uint_as_float(f2tf32(v.z));
            Bt[c + 3][r] = __uint_as_float(f2tf32(v.w));
        }
        __syncthreads();
#pragma unroll
        for (int kk = 0; kk < 4; kk++) {
            const int k = kk * 8;
            unsigned a[2][4], b[8][2];
#pragma unroll
            for (int mt = 0; mt < 2; mt++) {
                int rw = wm * 32 + mt * 16 + gid;
                a[mt][0] = __float_as_uint(As[rw][k + qid]);
                a[mt][1] = __float_as_uint(As[rw + 8][k + qid]);
                a[mt][2] = __float_as_uint(As[rw][k + 4 + qid]);
                a[mt][3] = __float_as_uint(As[rw + 8][k + 4 + qid]);
            }
#pragma unroll
            for (int nt = 0; nt < 8; nt++) {
                int cl = wn * 64 + nt * 8 + gid;
                b[nt][0] = __float_as_uint(Bt[cl][k + qid]);
                b[nt][1] = __float_as_uint(Bt[cl][k + 4 + qid]);
            }
#pragma unroll
            for (int mt = 0; mt < 2; mt++)
#pragma unroll
                for (int nt = 0; nt < 8; nt++) {
                    asm volatile(
                        "mma.sync.aligned.m16n8k8.row.col.f32.tf32.tf32.f32 "
                        "{%0,%1,%2,%3}, {%4,%5,%6,%7}, {%8,%9}, {%0,%1,%2,%3};\n"
                        : "+f"(acc[mt][nt][0]), "+f"(acc[mt][nt][1]),
                          "+f"(acc[mt][nt][2]), "+f"(acc[mt][nt][3])
                        : "r"(a[mt][0]), "r"(a[mt][1]), "r"(a[mt][2]), "r"(a[mt][3]),
                          "r"(b[nt][0]), "r"(b[nt][1]));
                }
        }
        __syncthreads();
    }
#pragma unroll
    for (int mt = 0; mt < 2; mt++) {
        int rw = row0 + wm * 32 + mt * 16 + gid;
#pragma unroll
        for (int nt = 0; nt < 8; nt++) {
            int cl = wn * 64 + nt * 8 + qid * 2;
            if (rw < NN)
                *(float2*)(g_hp1 + (size_t)rw * H1DIM + cl) =
                    make_float2(acc[mt][nt][0], acc[mt][nt][1]);
            if (rw + 8 < NN)
                *(float2*)(g_hp1 + (size_t)(rw + 8) * H1DIM + cl) =
                    make_float2(acc[mt][nt][2], acc[mt][nt][3]);
        }
    }
}

// ---------------------------------------------------------------------------
// alpha1: per-node attention logits. One warp per node.
// ---------------------------------------------------------------------------
__global__ void alpha1_kernel(const float* __restrict__ att_src, const float* __restrict__ att_dst) {
    int gw = (blockIdx.x * blockDim.x + threadIdx.x) >> 5;
    int lane = threadIdx.x & 31;
    if (gw >= NN) return;
    int head = lane >> 2, sub = lane & 3;
    float4 h = *(const float4*)(g_hp1 + (size_t)gw * H1DIM + lane * 4);
    const float* As = att_src + head * 16 + sub * 4;
    const float* Ad = att_dst + head * 16 + sub * 4;
    float s = h.x * As[0] + h.y * As[1] + h.z * As[2] + h.w * As[3];
    float d = h.x * Ad[0] + h.y * Ad[1] + h.z * Ad[2] + h.w * Ad[3];
    s += __shfl_xor_sync(0xffffffffu, s, 1);
    s += __shfl_xor_sync(0xffffffffu, s, 2);
    d += __shfl_xor_sync(0xffffffffu, d, 1);
    d += __shfl_xor_sync(0xffffffffu, d, 2);
    if (sub == 0) { g_as1[gw * 8 + head] = s; g_ad1[gw * 8 + head] = d; }
}

// ---------------------------------------------------------------------------
// agg1: CSR gather + softmax-normalize + bias + ELU. One warp per dst node.
// All lanes compute their own head weight (no shfl in loop); unroll x4.
// ---------------------------------------------------------------------------
__device__ __forceinline__ float edge_w1(int s, int head, float myad) {
    float t = __ldg(g_as1 + s * 8 + head) + myad;
    t = t > 0.f ? t : 0.2f * t;
    return __expf(t);
}

__global__ void __launch_bounds__(256) agg1_kernel(const float* __restrict__ b1) {
    int gw = (blockIdx.x * blockDim.x + threadIdx.x) >> 5;
    int lane = threadIdx.x & 31;
    if (gw >= NN) return;
    int head = lane >> 2;
    int beg = g_off[gw], end = g_off[gw + 1];
    float myad = g_ad1[gw * 8 + head];
    float a0 = 0.f, a1 = 0.f, a2 = 0.f, a3 = 0.f, den = 0.f;
    int p = beg;
    for (; p + 4 <= end; p += 4) {
        int s0 = g_eidx[p], s1 = g_eidx[p + 1], s2 = g_eidx[p + 2], s3 = g_eidx[p + 3];
        float w0 = edge_w1(s0, head, myad);
        float w1 = edge_w1(s1, head, myad);
        float w2 = edge_w1(s2, head, myad);
        float w3 = edge_w1(s3, head, myad);
        float4 h0 = *(const float4*)(g_hp1 + (size_t)s0 * H1DIM + lane * 4);
        float4 h1 = *(const float4*)(g_hp1 + (size_t)s1 * H1DIM + lane * 4);
        float4 h2 = *(const float4*)(g_hp1 + (size_t)s2 * H1DIM + lane * 4);
        float4 h3 = *(const float4*)(g_hp1 + (size_t)s3 * H1DIM + lane * 4);
        den += (w0 + w1) + (w2 + w3);
        a0 += w0 * h0.x + w1 * h1.x + w2 * h2.x + w3 * h3.x;
        a1 += w0 * h0.y + w1 * h1.y + w2 * h2.y + w3 * h3.y;
        a2 += w0 * h0.z + w1 * h1.z + w2 * h2.z + w3 * h3.z;
        a3 += w0 * h0.w + w1 * h1.w + w2 * h2.w + w3 * h3.w;
    }
    for (; p < end; p++) {
        int s = g_eidx[p];
        float w = edge_w1(s, head, myad);
        float4 h = *(const float4*)(g_hp1 + (size_t)s * H1DIM + lane * 4);
        den += w;
        a0 += w * h.x; a1 += w * h.y; a2 += w * h.z; a3 += w * h.w;
    }
    float inv = __frcp_rn(den);
    const float* bb = b1 + lane * 4;
    float v0 = a0 * inv + bb[0];
    float v1 = a1 * inv + bb[1];
    float v2 = a2 * inv + bb[2];
    float v3 = a3 * inv + bb[3];
    v0 = v0 > 0.f ? v0 : expm1f(v0);
    v1 = v1 > 0.f ? v1 : expm1f(v1);
    v2 = v2 > 0.f ? v2 : expm1f(v2);
    v3 = v3 > 0.f ? v3 : expm1f(v3);
    *(float4*)(g_h1 + (size_t)gw * H1DIM + lane * 4) = make_float4(v0, v1, v2, v3);
}

// ---------------------------------------------------------------------------
// GEMM2 + alpha2 fused
// ---------------------------------------------------------------------------
__global__ void __launch_bounds__(256) gemm2_kernel(const float* __restrict__ W2,
                             const float* __restrict__ as2w, const float* __restrict__ ad2w) {
    __shared__ __align__(16) float Ws[128 * 16];
    __shared__ __align__(16) float Hs[16][132];
    const int tid = threadIdx.x;
    const int row0 = blockIdx.x * 16;
#pragma unroll
    for (int t = 0; t < 2; t++) {
        int i = (tid + t * 256) * 4;
        *(float4*)&Ws[i] = *(const float4*)(W2 + i);
    }
#pragma unroll
    for (int t = 0; t < 2; t++) {
        int i = tid + t * 256;
        int r = i >> 5, c = (i & 31) << 2;
        float4 v = make_float4(0.f, 0.f, 0.f, 0.f);
        int gr = row0 + r;
        if (gr < NN) v = *(const float4*)(g_h1 + (size_t)gr * H1DIM + c);
        *(float4*)&Hs[r][c] = v;
    }
    __syncthreads();
    const int r = tid >> 4, c = tid & 15;
    float s = 0.f;
#pragma unroll
    for (int k = 0; k < 128; k++) s += Hs[r][k] * Ws[k * 16 + c];
    float sv = s * as2w[c], dv = s * ad2w[c];
#pragma unroll
    for (int off = 8; off >= 1; off >>= 1) {
        sv += __shfl_down_sync(0xffffffffu, sv, off, 16);
        dv += __shfl_down_sync(0xffffffffu, dv, off, 16);
    }
    int gr = row0 + r;
    if (gr < NN) {
        g_h2[gr * 16 + c] = s;
        if (c == 0) { g_as2[gr] = sv; g_ad2[gr] = dv; }
    }
}

// ---------------------------------------------------------------------------
// agg2: one warp per dst node; two 16-lane groups; unroll x2.
// ---------------------------------------------------------------------------
__global__ void __launch_bounds__(256) agg2_kernel(const float* __restrict__ b2,
                                                   float* __restrict__ out) {
    int gw = (blockIdx.x * blockDim.x + threadIdx.x) >> 5;
    int lane = threadIdx.x & 31;
    if (gw >= NN) return;
    int beg = g_off[gw], end = g_off[gw + 1];
    int grp = lane >> 4, fl = lane & 15;
    float ad = g_ad2[gw];
    float acc = 0.f, den = 0.f;
    int p = beg + grp;
    for (; p + 2 < end; p += 4) {
        int s0 = g_eidx[p], s1 = g_eidx[p + 2];
        float t0 = g_as2[s0] + ad, t1 = g_as2[s1] + ad;
        t0 = t0 > 0.f ? t0 : 0.2f * t0;
        t1 = t1 > 0.f ? t1 : 0.2f * t1;
        float w0 = __expf(t0), w1 = __expf(t1);
        float v0 = g_h2[s0 * 16 + fl], v1 = g_h2[s1 * 16 + fl];
        den += w0 + w1;
        acc += w0 * v0 + w1 * v1;
    }
    if (p < end) {
        int s = g_eidx[p];
        float t = g_as2[s] + ad;
        t = t > 0.f ? t : 0.2f * t;
        float w = __expf(t);
        den += w;
        acc += w * g_h2[s * 16 + fl];
    }
    acc += __shfl_xor_sync(0xffffffffu, acc, 16);
    den += __shfl_xor_sync(0xffffffffu, den, 16);
    if (grp == 0) out[gw * 16 + fl] = acc * __frcp_rn(den) + b2[fl];
}

// ---------------------------------------------------------------------------
extern "C" void kernel_launch(void* const* d_in, const int* in_sizes, int n_in,
                              void* d_out, int out_size) {
    const float* x   = (const float*)d_in[0];
    const int*   ei  = (const int*)d_in[1];
    const float* W1  = (const float*)d_in[2];
    const float* as1 = (const float*)d_in[3];
    const float* ad1 = (const float*)d_in[4];
    const float* b1  = (const float*)d_in[5];
    const float* W2  = (const float*)d_in[6];
    const float* as2 = (const float*)d_in[7];
    const float* ad2 = (const float*)d_in[8];
    const float* b2  = (const float*)d_in[9];
    const int E = in_sizes[1] / 2;
    const int scat_threads = (E >> 1) + NN + 1;

    zero_deg_kernel<<<(NN + 255) / 256, 256>>>();
    hist_kernel<<<((E + 3) / 4 + 255) / 256, 256>>>(ei, E);
    scanA_kernel<<<NBLK, 256>>>();
    scanB_kernel<<<1, 256>>>();
    scanC_kernel<<<NBLK, 256>>>();
    scatter_kernel<<<(scat_threads + 255) / 256, 256>>>(ei, E);

    gemm1_kernel<<<(NN + 127) / 128, 256>>>(x, W1);
    alpha1_kernel<<<(NN * 32 + 255) / 256, 256>>>(as1, ad1);
    agg1_kernel<<<(NN * 32 + 255) / 256, 256>>>(b1);
    gemm2_kernel<<<(NN + 15) / 16, 256>>>(W2, as2, ad2);
    agg2_kernel<<<(NN * 32 + 255) / 256, 256>>>(b2, (float*)d_out);
}